// round 4
// baseline (speedup 1.0000x reference)
#include <cuda_runtime.h>

#define BB 64
#define NP 1024
#define LL 64
#define HH 128
#define W1K 67           // 3 + L (W1 row length)
#define ROW 132          // padded smem row (floats)
#define TN 128           // points per MLP tile

// packed f32x2 helpers (Blackwell FFMA2 path; PTX fma.rn.f32x2)
#define FMA2(d, a, b, c) \
    asm("fma.rn.f32x2 %0, %1, %2, %3;" : "=l"(d) : "l"(a), "l"(b), "l"(c))
#define PACKF2(d, lo, hi) \
    asm("mov.b64 %0, {%1, %2};" : "=l"(d) \
        : "r"(__float_as_uint(lo)), "r"(__float_as_uint(hi)))
#define UNPACKF2(lo, hi, s) do { unsigned int _ulo, _uhi; \
    asm("mov.b64 {%0, %1}, %2;" : "=r"(_ulo), "=r"(_uhi) : "l"(s)); \
    lo = __uint_as_float(_ulo); hi = __uint_as_float(_uhi); } while (0)

__device__ float g_acc[3];        // [0]=chamfer dir0, [1]=dir1, [2]=l2
__device__ float g_w1l[BB * HH];  // per-batch latent part of layer 1 + b1

__global__ void init_kernel() {
    if (threadIdx.x < 3) g_acc[threadIdx.x] = 0.0f;
}

// W1L[b][o] = b1[o] + sum_l W1[o][3+l] * latent[b][l]
__global__ void __launch_bounds__(128) w1l_kernel(
    const float* __restrict__ latent, const float* __restrict__ W1,
    const float* __restrict__ b1)
{
    __shared__ float slat[LL];
    const int b = blockIdx.x, o = threadIdx.x;
    if (o < LL) slat[o] = latent[b * LL + o];
    __syncthreads();
    float acc = b1[o];
    const float* wrow = W1 + o * W1K + 3;
    #pragma unroll 8
    for (int l = 0; l < LL; l++) acc = fmaf(wrow[l], slat[l], acc);
    g_w1l[b * HH + o] = acc;
}

__device__ __forceinline__ float block_sum(float v, float* scratch) {
    #pragma unroll
    for (int off = 16; off; off >>= 1) v += __shfl_down_sync(0xffffffffu, v, off);
    int lane = threadIdx.x & 31, w = threadIdx.x >> 5;
    if (lane == 0) scratch[w] = v;
    __syncthreads();
    int nw = blockDim.x >> 5;
    v = (threadIdx.x < nw) ? scratch[threadIdx.x] : 0.0f;
    if (w == 0) {
        #pragma unroll
        for (int off = 16; off; off >>= 1) v += __shfl_down_sync(0xffffffffu, v, off);
    }
    return v;  // valid on thread 0
}

// ---------------------------------------------------------------------------
// MLP: h1 = relu(W1pc @ pc + W1L[b]); h2 = relu(W2 @ h1 + b2);
// noise = W3 @ h2 + b3; pc_est = pc - noise; accumulate L2 loss.
// One CTA = 128 points of one batch. 256 threads, 8x8 microtiles.
// GEMM2 mainloop uses packed f32x2 FMA (FFMA2) for 2x fp32 throughput.
// ---------------------------------------------------------------------------
__global__ void __launch_bounds__(256) mlp_kernel(
    const float* __restrict__ pc, const float* __restrict__ pc_gt,
    const float* __restrict__ W1,
    const float* __restrict__ W2, const float* __restrict__ b2,
    const float* __restrict__ W3, const float* __restrict__ b3,
    float* __restrict__ out_est)
{
    extern __shared__ float sm[];
    float* s_w2 = sm;                    // [HH][ROW]  W2^T: [k][o]
    float* s_h  = sm + HH * ROW;         // [HH][ROW]  h1 then h2, [k][n]
    float* s_wx = s_h + HH * ROW;        // [3][ROW]   W1 pc-part, [k][o]
    float* s_x  = s_wx + 3 * ROW;        // [3][ROW]   pc tile, [k][n]
    float* s_e  = s_x + 3 * ROW;
    float* swl  = s_e;            // 128 : W1L row for this batch
    float* sb2  = s_e + 128;      // 128
    float* sw3  = s_e + 256;      // 384
    float* sb3  = s_e + 640;      // 4
    float* sred = s_e + 644;      // 32

    const int tid = threadIdx.x;
    const int b   = blockIdx.x >> 3;
    const int n0  = (blockIdx.x & 7) * TN;

    // ---- stage: pc tile, W1 pc-columns, W1L, W2^T, b2, W3, b3 ----
    for (int i = tid; i < 3 * TN; i += 256) {
        int k = i >> 7, n = i & 127;
        s_x[k * ROW + n] = pc[(b * 3 + k) * NP + n0 + n];
    }
    if (tid < 128) {
        s_wx[0 * ROW + tid] = W1[tid * W1K + 0];
        s_wx[1 * ROW + tid] = W1[tid * W1K + 1];
        s_wx[2 * ROW + tid] = W1[tid * W1K + 2];
        swl[tid] = g_w1l[b * HH + tid];
        sb2[tid] = b2[tid];
    }
    for (int i = tid; i < 384; i += 256) sw3[i] = W3[i];
    if (tid < 3) sb3[tid] = b3[tid];
    for (int i = tid; i < HH * HH; i += 256) {
        int o = i >> 7, k = i & 127;
        s_w2[k * ROW + o] = W2[i];
    }
    __syncthreads();

    const int tn = (tid & 15) * 8;
    const int to = (tid >> 4) * 8;

    // ---- layer 1: 3-deep GEMM + precomputed latent term ----
    {
        float acc[8][8];
        #pragma unroll
        for (int i = 0; i < 8; i++)
            #pragma unroll
            for (int j = 0; j < 8; j++) acc[i][j] = 0.0f;
        #pragma unroll
        for (int k = 0; k < 3; k++) {
            float4 a0 = *(const float4*)&s_wx[k * ROW + to];
            float4 a1 = *(const float4*)&s_wx[k * ROW + to + 4];
            float4 c0 = *(const float4*)&s_x[k * ROW + tn];
            float4 c1 = *(const float4*)&s_x[k * ROW + tn + 4];
            float a[8] = {a0.x, a0.y, a0.z, a0.w, a1.x, a1.y, a1.z, a1.w};
            float c[8] = {c0.x, c0.y, c0.z, c0.w, c1.x, c1.y, c1.z, c1.w};
            #pragma unroll
            for (int i = 0; i < 8; i++)
                #pragma unroll
                for (int j = 0; j < 8; j++) acc[i][j] = fmaf(a[i], c[j], acc[i][j]);
        }
        #pragma unroll
        for (int i = 0; i < 8; i++) {
            float bi = swl[to + i];
            #pragma unroll
            for (int j = 0; j < 8; j++)
                s_h[(to + i) * ROW + tn + j] = fmaxf(acc[i][j] + bi, 0.0f);
        }
    }
    __syncthreads();

    // ---- layer 2: 128x128x128 GEMM, packed f32x2 ----
    {
        unsigned long long acc2[8][4];   // acc2[i][jp] = (acc[i][2jp], acc[i][2jp+1])
        #pragma unroll
        for (int i = 0; i < 8; i++)
            #pragma unroll
            for (int jp = 0; jp < 4; jp++) acc2[i][jp] = 0ULL;  // (0.0f, 0.0f)

        for (int k = 0; k < HH; k++) {
            float4 a0 = *(const float4*)&s_w2[k * ROW + to];
            float4 a1 = *(const float4*)&s_w2[k * ROW + to + 4];
            float4 c0 = *(const float4*)&s_h[k * ROW + tn];
            float4 c1 = *(const float4*)&s_h[k * ROW + tn + 4];
            unsigned long long cp[4];
            PACKF2(cp[0], c0.x, c0.y);
            PACKF2(cp[1], c0.z, c0.w);
            PACKF2(cp[2], c1.x, c1.y);
            PACKF2(cp[3], c1.z, c1.w);
            float a[8] = {a0.x, a0.y, a0.z, a0.w, a1.x, a1.y, a1.z, a1.w};
            #pragma unroll
            for (int i = 0; i < 8; i++) {
                unsigned long long ap;
                PACKF2(ap, a[i], a[i]);
                #pragma unroll
                for (int jp = 0; jp < 4; jp++)
                    FMA2(acc2[i][jp], ap, cp[jp], acc2[i][jp]);
            }
        }
        __syncthreads();   // all h1 reads done; overwrite s_h with h2
        #pragma unroll
        for (int i = 0; i < 8; i++) {
            float bi = sb2[to + i];
            #pragma unroll
            for (int jp = 0; jp < 4; jp++) {
                float lo, hi;
                UNPACKF2(lo, hi, acc2[i][jp]);
                s_h[(to + i) * ROW + tn + 2 * jp]     = fmaxf(lo + bi, 0.0f);
                s_h[(to + i) * ROW + tn + 2 * jp + 1] = fmaxf(hi + bi, 0.0f);
            }
        }
    }
    __syncthreads();

    // ---- layer 3 (3x128) + epilogue: pc_est + L2 partial ----
    float l2v = 0.0f;
    if (tid < TN) {
        int n = tid, g = n0 + n;
        float o0 = sb3[0], o1 = sb3[1], o2 = sb3[2];
        #pragma unroll 4
        for (int k = 0; k < HH; k++) {
            float hv = s_h[k * ROW + n];
            o0 = fmaf(sw3[k], hv, o0);
            o1 = fmaf(sw3[128 + k], hv, o1);
            o2 = fmaf(sw3[256 + k], hv, o2);
        }
        int base = (b * 3) * NP + g;
        float e0 = pc[base] - o0;
        float e1 = pc[base + NP] - o1;
        float e2 = pc[base + 2 * NP] - o2;
        out_est[base] = e0;
        out_est[base + NP] = e1;
        out_est[base + 2 * NP] = e2;
        float d0 = pc_gt[base] - e0;
        float d1 = pc_gt[base + NP] - e1;
        float d2 = pc_gt[base + 2 * NP] - e2;
        l2v = fmaf(d0, d0, fmaf(d1, d1, d2 * d2));
    }
    __syncthreads();
    float s = block_sum(l2v, sred);
    if (tid == 0) atomicAdd(&g_acc[2], s);
}

// ---------------------------------------------------------------------------
// Chamfer via d = a^2 + b^2 - 2*dot (exact same formula as reference).
// SMEM holds float4 {x, y, z, |p|^2} per opposing point; min_m d =
// a2 + min_m(b2[m] - 2 dot(a, p[m])) -> 1 LDS.128 + 3 FMA + 1 FMNMX per point.
// grid = (4 row-tiles, 64 batches, 2 directions), 256 threads.
// ---------------------------------------------------------------------------
__global__ void __launch_bounds__(256) chamfer_kernel(
    const float* __restrict__ pc_gt, const float* __restrict__ est)
{
    __shared__ float4 spts[NP];
    __shared__ float sred[8];
    const int b = blockIdx.y;
    const int dir = blockIdx.z;
    const float* rows  = dir ? est   : pc_gt;
    const float* other = dir ? pc_gt : est;
    const int base = b * 3 * NP;

    for (int i = threadIdx.x; i < NP; i += 256) {
        float x = other[base + i];
        float y = other[base + NP + i];
        float z = other[base + 2 * NP + i];
        spts[i] = make_float4(x, y, z, fmaf(x, x, fmaf(y, y, z * z)));
    }
    __syncthreads();

    const int n = blockIdx.x * 256 + threadIdx.x;
    const float ax = rows[base + n];
    const float ay = rows[base + NP + n];
    const float az = rows[base + 2 * NP + n];
    const float a2 = fmaf(ax, ax, fmaf(ay, ay, az * az));
    const float axm2 = -2.0f * ax;
    const float aym2 = -2.0f * ay;
    const float azm2 = -2.0f * az;

    float best0 = 3.4e38f, best1 = 3.4e38f, best2 = 3.4e38f, best3 = 3.4e38f;
    #pragma unroll 2
    for (int m = 0; m < NP; m += 4) {
        float4 p0 = spts[m];
        float4 p1 = spts[m + 1];
        float4 p2 = spts[m + 2];
        float4 p3 = spts[m + 3];
        float t0 = fmaf(azm2, p0.z, fmaf(aym2, p0.y, fmaf(axm2, p0.x, p0.w)));
        float t1 = fmaf(azm2, p1.z, fmaf(aym2, p1.y, fmaf(axm2, p1.x, p1.w)));
        float t2 = fmaf(azm2, p2.z, fmaf(aym2, p2.y, fmaf(axm2, p2.x, p2.w)));
        float t3 = fmaf(azm2, p3.z, fmaf(aym2, p3.y, fmaf(axm2, p3.x, p3.w)));
        best0 = fminf(best0, t0);
        best1 = fminf(best1, t1);
        best2 = fminf(best2, t2);
        best3 = fminf(best3, t3);
    }
    float best = fminf(fminf(best0, best1), fminf(best2, best3));
    float s = block_sum(a2 + best, sred);
    if (threadIdx.x == 0) atomicAdd(&g_acc[dir], s);
}

__global__ void final_kernel(float* __restrict__ out) {
    float ch = (g_acc[0] + g_acc[1]) * (1.0f / (float)(BB * NP));
    float l2 = g_acc[2] * (1.0f / (float)(BB * 3 * NP));
    out[0] = 0.1f * ch + 0.9f * l2;
    out[1] = ch;
    out[2] = l2;
}

extern "C" void kernel_launch(void* const* d_in, const int* in_sizes, int n_in,
                              void* d_out, int out_size) {
    const float* pc    = (const float*)d_in[0];
    const float* pc_gt = (const float*)d_in[1];
    const float* lat   = (const float*)d_in[2];
    const float* W1    = (const float*)d_in[3];
    const float* b1    = (const float*)d_in[4];
    const float* W2    = (const float*)d_in[5];
    const float* b2    = (const float*)d_in[6];
    const float* W3    = (const float*)d_in[7];
    const float* b3    = (const float*)d_in[8];
    float* out = (float*)d_out;

    size_t smem = (size_t)(2 * HH * ROW + 6 * ROW + 676) * sizeof(float);
    (void)cudaFuncSetAttribute(mlp_kernel,
                               cudaFuncAttributeMaxDynamicSharedMemorySize,
                               (int)smem);

    init_kernel<<<1, 32>>>();
    w1l_kernel<<<BB, 128>>>(lat, W1, b1);
    mlp_kernel<<<BB * (NP / TN), 256, smem>>>(pc, pc_gt, W1, W2, b2, W3, b3,
                                              out + 3);
    chamfer_kernel<<<dim3(NP / 256, BB, 2), 256>>>(pc_gt, out + 3);
    final_kernel<<<1, 1>>>(out);
}

// round 5
// speedup vs baseline: 1.1886x; 1.1886x over previous
#include <cuda_runtime.h>

#define BB 64
#define NP 1024
#define LL 64
#define HH 128
#define W1K 67           // 3 + L (W1 row length)
#define ROW 132          // padded smem row (floats)
#define TN 128           // points per MLP tile

__device__ float g_acc[3];        // [0]=chamfer dir0, [1]=dir1, [2]=l2
__device__ float g_w1l[BB * HH];  // per-batch latent part of layer 1 + b1

__global__ void init_kernel() {
    if (threadIdx.x < 3) g_acc[threadIdx.x] = 0.0f;
}

// W1L[b][o] = b1[o] + sum_l W1[o][3+l] * latent[b][l]
__global__ void __launch_bounds__(128) w1l_kernel(
    const float* __restrict__ latent, const float* __restrict__ W1,
    const float* __restrict__ b1)
{
    __shared__ float slat[LL];
    const int b = blockIdx.x, o = threadIdx.x;
    if (o < LL) slat[o] = latent[b * LL + o];
    __syncthreads();
    float acc = b1[o];
    const float* wrow = W1 + o * W1K + 3;
    #pragma unroll 8
    for (int l = 0; l < LL; l++) acc = fmaf(wrow[l], slat[l], acc);
    g_w1l[b * HH + o] = acc;
}

__device__ __forceinline__ float block_sum(float v, float* scratch) {
    #pragma unroll
    for (int off = 16; off; off >>= 1) v += __shfl_down_sync(0xffffffffu, v, off);
    int lane = threadIdx.x & 31, w = threadIdx.x >> 5;
    if (lane == 0) scratch[w] = v;
    __syncthreads();
    int nw = blockDim.x >> 5;
    v = (threadIdx.x < nw) ? scratch[threadIdx.x] : 0.0f;
    if (w == 0) {
        #pragma unroll
        for (int off = 16; off; off >>= 1) v += __shfl_down_sync(0xffffffffu, v, off);
    }
    return v;  // valid on thread 0
}

// ---------------------------------------------------------------------------
// MLP: h1 = relu(W1pc @ pc + W1L[b]); h2 = relu(W2 @ h1 + b2);
// noise = W3 @ h2 + b3; pc_est = pc - noise; accumulate L2 loss.
// One CTA = 128 points of one batch. 256 threads, 8x8 microtiles.
// ---------------------------------------------------------------------------
__global__ void __launch_bounds__(256) mlp_kernel(
    const float* __restrict__ pc, const float* __restrict__ pc_gt,
    const float* __restrict__ W1,
    const float* __restrict__ W2, const float* __restrict__ b2,
    const float* __restrict__ W3, const float* __restrict__ b3,
    float* __restrict__ out_est)
{
    extern __shared__ float sm[];
    float* s_w2 = sm;                    // [HH][ROW]  W2^T: [k][o]
    float* s_h  = sm + HH * ROW;         // [HH][ROW]  h1 then h2, [k][n]
    float* s_wx = s_h + HH * ROW;        // [3][ROW]   W1 pc-part, [k][o]
    float* s_x  = s_wx + 3 * ROW;        // [3][ROW]   pc tile, [k][n]
    float* s_e  = s_x + 3 * ROW;
    float* swl  = s_e;            // 128 : W1L row for this batch
    float* sb2  = s_e + 128;      // 128
    float* sw3  = s_e + 256;      // 384
    float* sb3  = s_e + 640;      // 4
    float* sred = s_e + 644;      // 32

    const int tid = threadIdx.x;
    const int b   = blockIdx.x >> 3;
    const int n0  = (blockIdx.x & 7) * TN;

    // ---- stage: pc tile, W1 pc-columns, W1L, W2^T, b2, W3, b3 ----
    for (int i = tid; i < 3 * TN; i += 256) {
        int k = i >> 7, n = i & 127;
        s_x[k * ROW + n] = pc[(b * 3 + k) * NP + n0 + n];
    }
    if (tid < 128) {
        s_wx[0 * ROW + tid] = W1[tid * W1K + 0];
        s_wx[1 * ROW + tid] = W1[tid * W1K + 1];
        s_wx[2 * ROW + tid] = W1[tid * W1K + 2];
        swl[tid] = g_w1l[b * HH + tid];
        sb2[tid] = b2[tid];
    }
    for (int i = tid; i < 384; i += 256) sw3[i] = W3[i];
    if (tid < 3) sb3[tid] = b3[tid];
    for (int i = tid; i < HH * HH; i += 256) {
        int o = i >> 7, k = i & 127;
        s_w2[k * ROW + o] = W2[i];
    }
    __syncthreads();

    const int tn = (tid & 15) * 8;
    const int to = (tid >> 4) * 8;

    float acc[8][8];
    #pragma unroll
    for (int i = 0; i < 8; i++)
        #pragma unroll
        for (int j = 0; j < 8; j++) acc[i][j] = 0.0f;

    // ---- layer 1: 3-deep GEMM + precomputed latent term ----
    #pragma unroll
    for (int k = 0; k < 3; k++) {
        float4 a0 = *(const float4*)&s_wx[k * ROW + to];
        float4 a1 = *(const float4*)&s_wx[k * ROW + to + 4];
        float4 c0 = *(const float4*)&s_x[k * ROW + tn];
        float4 c1 = *(const float4*)&s_x[k * ROW + tn + 4];
        float a[8] = {a0.x, a0.y, a0.z, a0.w, a1.x, a1.y, a1.z, a1.w};
        float c[8] = {c0.x, c0.y, c0.z, c0.w, c1.x, c1.y, c1.z, c1.w};
        #pragma unroll
        for (int i = 0; i < 8; i++)
            #pragma unroll
            for (int j = 0; j < 8; j++) acc[i][j] = fmaf(a[i], c[j], acc[i][j]);
    }
    #pragma unroll
    for (int i = 0; i < 8; i++) {
        float bi = swl[to + i];
        #pragma unroll
        for (int j = 0; j < 8; j++)
            s_h[(to + i) * ROW + tn + j] = fmaxf(acc[i][j] + bi, 0.0f);
    }
    __syncthreads();

    #pragma unroll
    for (int i = 0; i < 8; i++)
        #pragma unroll
        for (int j = 0; j < 8; j++) acc[i][j] = 0.0f;

    // ---- layer 2: 128x128x128 GEMM ----
    for (int k = 0; k < HH; k++) {
        float4 a0 = *(const float4*)&s_w2[k * ROW + to];
        float4 a1 = *(const float4*)&s_w2[k * ROW + to + 4];
        float4 c0 = *(const float4*)&s_h[k * ROW + tn];
        float4 c1 = *(const float4*)&s_h[k * ROW + tn + 4];
        float a[8] = {a0.x, a0.y, a0.z, a0.w, a1.x, a1.y, a1.z, a1.w};
        float c[8] = {c0.x, c0.y, c0.z, c0.w, c1.x, c1.y, c1.z, c1.w};
        #pragma unroll
        for (int i = 0; i < 8; i++)
            #pragma unroll
            for (int j = 0; j < 8; j++) acc[i][j] = fmaf(a[i], c[j], acc[i][j]);
    }
    __syncthreads();   // all h1 reads done; overwrite s_h with h2
    #pragma unroll
    for (int i = 0; i < 8; i++) {
        float bi = sb2[to + i];
        #pragma unroll
        for (int j = 0; j < 8; j++)
            s_h[(to + i) * ROW + tn + j] = fmaxf(acc[i][j] + bi, 0.0f);
    }
    __syncthreads();

    // ---- layer 3 (3x128) + epilogue: pc_est + L2 partial ----
    float l2v = 0.0f;
    if (tid < TN) {
        int n = tid, g = n0 + n;
        float o0 = sb3[0], o1 = sb3[1], o2 = sb3[2];
        #pragma unroll 4
        for (int k = 0; k < HH; k++) {
            float hv = s_h[k * ROW + n];
            o0 = fmaf(sw3[k], hv, o0);
            o1 = fmaf(sw3[128 + k], hv, o1);
            o2 = fmaf(sw3[256 + k], hv, o2);
        }
        int base = (b * 3) * NP + g;
        float e0 = pc[base] - o0;
        float e1 = pc[base + NP] - o1;
        float e2 = pc[base + 2 * NP] - o2;
        out_est[base] = e0;
        out_est[base + NP] = e1;
        out_est[base + 2 * NP] = e2;
        float d0 = pc_gt[base] - e0;
        float d1 = pc_gt[base + NP] - e1;
        float d2 = pc_gt[base + 2 * NP] - e2;
        l2v = fmaf(d0, d0, fmaf(d1, d1, d2 * d2));
    }
    __syncthreads();
    float s = block_sum(l2v, sred);
    if (tid == 0) atomicAdd(&g_acc[2], s);
}

// ---------------------------------------------------------------------------
// Chamfer via d = a^2 + b^2 - 2*dot. Each THREAD carries 4 query points so
// every spts[m] LDS.128 is amortized over 4 dot products (LDS pressure /4).
// grid = (64 batches, 2 directions), 256 threads; 128 CTAs = single wave.
// ---------------------------------------------------------------------------
__global__ void __launch_bounds__(256) chamfer_kernel(
    const float* __restrict__ pc_gt, const float* __restrict__ est)
{
    __shared__ float4 spts[NP];
    __shared__ float sred[8];
    const int b = blockIdx.x;
    const int dir = blockIdx.y;
    const float* rows  = dir ? est   : pc_gt;
    const float* other = dir ? pc_gt : est;
    const int base = b * 3 * NP;

    for (int i = threadIdx.x; i < NP; i += 256) {
        float x = other[base + i];
        float y = other[base + NP + i];
        float z = other[base + 2 * NP + i];
        spts[i] = make_float4(x, y, z, fmaf(x, x, fmaf(y, y, z * z)));
    }
    __syncthreads();

    // 4 query points per thread
    float qx[4], qy[4], qz[4], qa2[4];
    #pragma unroll
    for (int q = 0; q < 4; q++) {
        int n = threadIdx.x + q * 256;
        float ax = rows[base + n];
        float ay = rows[base + NP + n];
        float az = rows[base + 2 * NP + n];
        qa2[q] = fmaf(ax, ax, fmaf(ay, ay, az * az));
        qx[q] = -2.0f * ax;
        qy[q] = -2.0f * ay;
        qz[q] = -2.0f * az;
    }

    float bst[4][2];
    #pragma unroll
    for (int q = 0; q < 4; q++) { bst[q][0] = 3.4e38f; bst[q][1] = 3.4e38f; }

    for (int m = 0; m < NP; m += 4) {
        float4 p0 = spts[m];
        float4 p1 = spts[m + 1];
        float4 p2 = spts[m + 2];
        float4 p3 = spts[m + 3];
        #pragma unroll
        for (int q = 0; q < 4; q++) {
            float t0 = fmaf(qz[q], p0.z, fmaf(qy[q], p0.y, fmaf(qx[q], p0.x, p0.w)));
            float t1 = fmaf(qz[q], p1.z, fmaf(qy[q], p1.y, fmaf(qx[q], p1.x, p1.w)));
            float t2 = fmaf(qz[q], p2.z, fmaf(qy[q], p2.y, fmaf(qx[q], p2.x, p2.w)));
            float t3 = fmaf(qz[q], p3.z, fmaf(qy[q], p3.y, fmaf(qx[q], p3.x, p3.w)));
            bst[q][0] = fminf(bst[q][0], fminf(t0, t1));
            bst[q][1] = fminf(bst[q][1], fminf(t2, t3));
        }
    }

    float acc = 0.0f;
    #pragma unroll
    for (int q = 0; q < 4; q++)
        acc += qa2[q] + fminf(bst[q][0], bst[q][1]);
    float s = block_sum(acc, sred);
    if (threadIdx.x == 0) atomicAdd(&g_acc[dir], s);
}

__global__ void final_kernel(float* __restrict__ out) {
    float ch = (g_acc[0] + g_acc[1]) * (1.0f / (float)(BB * NP));
    float l2 = g_acc[2] * (1.0f / (float)(BB * 3 * NP));
    out[0] = 0.1f * ch + 0.9f * l2;
    out[1] = ch;
    out[2] = l2;
}

extern "C" void kernel_launch(void* const* d_in, const int* in_sizes, int n_in,
                              void* d_out, int out_size) {
    const float* pc    = (const float*)d_in[0];
    const float* pc_gt = (const float*)d_in[1];
    const float* lat   = (const float*)d_in[2];
    const float* W1    = (const float*)d_in[3];
    const float* b1    = (const float*)d_in[4];
    const float* W2    = (const float*)d_in[5];
    const float* b2    = (const float*)d_in[6];
    const float* W3    = (const float*)d_in[7];
    const float* b3    = (const float*)d_in[8];
    float* out = (float*)d_out;

    size_t smem = (size_t)(2 * HH * ROW + 6 * ROW + 676) * sizeof(float);
    (void)cudaFuncSetAttribute(mlp_kernel,
                               cudaFuncAttributeMaxDynamicSharedMemorySize,
                               (int)smem);

    init_kernel<<<1, 32>>>();
    w1l_kernel<<<BB, 128>>>(lat, W1, b1);
    mlp_kernel<<<BB * (NP / TN), 256, smem>>>(pc, pc_gt, W1, W2, b2, W3, b3,
                                              out + 3);
    chamfer_kernel<<<dim3(BB, 2), 256>>>(pc_gt, out + 3);
    final_kernel<<<1, 1>>>(out);
}